// round 15
// baseline (speedup 1.0000x reference)
#include <cuda_runtime.h>
#include <cuda_bf16.h>
#include <math.h>

// Problem constants
#define SQ   256
#define BB   64
#define HH   512
#define IND  1024
#define BH   (BB*HH)      // 32768
#define SBH  (SQ*BB*HH)   // 8388608
#define OUT_SZ ((size_t)SQ*BB*2*HH)
#define NBLK 224          // persistent grid size
#define LDA  40           // bf16 per smem row (80 B): 20i mod 32 -> conflict-free ldmatrix

// ---------------- fp32 scratch ----------------
__device__ float g_h0 [2][2][BH];       // layer-0 hidden ping-pong [dir][parity]
__device__ float g_h1 [2][2][BH];       // layer-1 hidden ping-pong
__device__ float g_z  [2][2][BH];       // z gate
__device__ float g_pin[2][3][SBH];      // precomputed L0 input-half preact [d][gate]
__device__ float g_paL0[2][2][2][BH];   // L0 r/z recurrent partials [d][gate][slice]
__device__ float g_paL1[2][2][4][BH];   // L1 r/z partials [d][gate][slice]
__device__ float g_psp [2][2][BH];      // L1 s-input partials [d][slice]
__device__ float g_sp  [2][2][4][BH];   // s recurrent partials [layer][d][slice]
__device__ unsigned g_bar;              // grid barrier counter

// ---------------- bf16 split operands (hi + lo) ----------------
__device__ __align__(16) __nv_bfloat16 g_xh [SBH],        g_xl [SBH];
__device__ __align__(16) __nv_bfloat16 g_y0h[2][SBH],     g_y0l[2][SBH];
__device__ __align__(16) __nv_bfloat16 g_h0h[2][2][BH],   g_h0l[2][2][BH];
__device__ __align__(16) __nv_bfloat16 g_h1h[2][2][BH],   g_h1l[2][2][BH];
__device__ __align__(16) __nv_bfloat16 g_rhh[2][2][BH],   g_rhl[2][2][BH];
__device__ __align__(16) __nv_bfloat16 g_Wh[3][4*HH*IND], g_Wl[3][4*HH*IND]; // [gate r/z/s]

__device__ __forceinline__ float fsig(float x) { return 1.f / (1.f + __expf(-x)); }

__device__ __forceinline__ void bfsplit(float x, __nv_bfloat16& h, __nv_bfloat16& l)
{
    h = __float2bfloat16(x);
    l = __float2bfloat16(x - __bfloat162float(h));
}

__device__ __forceinline__ unsigned smem_u32(const void* p)
{
    return (unsigned)__cvta_generic_to_shared(p);
}

// ---------------- mma / ldmatrix / cp.async wrappers ----------------
__device__ __forceinline__ void mma_bf16(float* c, const unsigned* a, const unsigned* b)
{
    asm volatile(
        "mma.sync.aligned.m16n8k16.row.col.f32.bf16.bf16.f32 "
        "{%0,%1,%2,%3},{%4,%5,%6,%7},{%8,%9},{%0,%1,%2,%3};\n"
        : "+f"(c[0]), "+f"(c[1]), "+f"(c[2]), "+f"(c[3])
        : "r"(a[0]), "r"(a[1]), "r"(a[2]), "r"(a[3]), "r"(b[0]), "r"(b[1]));
}
__device__ __forceinline__ void ldsm4(unsigned* r, unsigned addr)
{
    asm volatile("ldmatrix.sync.aligned.m8n8.x4.shared.b16 {%0,%1,%2,%3},[%4];\n"
        : "=r"(r[0]), "=r"(r[1]), "=r"(r[2]), "=r"(r[3]) : "r"(addr));
}
__device__ __forceinline__ void cpa16(unsigned s, const void* g)
{
    asm volatile("cp.async.cg.shared.global [%0], [%1], 16;\n" :: "r"(s), "l"(g));
}
__device__ __forceinline__ void cpa_commit()
{
    asm volatile("cp.async.commit_group;\n");
}
template<int N> __device__ __forceinline__ void cpa_wait()
{
    asm volatile("cp.async.wait_group %0;\n" :: "n"(N));
}

// ---------------- grid-wide spin barrier ----------------
__device__ __forceinline__ void grid_bar(unsigned target)
{
    __threadfence();
    __syncthreads();
    if (threadIdx.x == 0) {
        atomicAdd(&g_bar, 1u);
        while (atomicAdd(&g_bar, 0u) < target)
            __nanosleep(64);
        __threadfence();   // acquire + L1 invalidate
    }
    __syncthreads();
}

// ---------------- embedding gather: write split x, reset barrier ----------------
__global__ void embed_kernel(const int* __restrict__ tok,
                             const float* __restrict__ emb)
{
    if (blockIdx.x == 0 && threadIdx.x == 0) g_bar = 0u;
    int row = blockIdx.x;
    int t = tok[row];
    float4 v = ((const float4*)(emb + (size_t)t * HH))[threadIdx.x];
    size_t base = (size_t)row * HH + threadIdx.x * 4;
    float xs[4] = {v.x, v.y, v.z, v.w};
    #pragma unroll
    for (int j = 0; j < 4; ++j)
        bfsplit(xs[j], g_xh[base + j], g_xl[base + j]);
}

__global__ void init_kernel()
{
    int i = blockIdx.x * blockDim.x + threadIdx.x;
    if (i < BH) {
        __nv_bfloat16 zb = __float2bfloat16(0.f);
        g_h0[0][0][i] = 0.f; g_h0[1][0][i] = 0.f;
        g_h1[0][0][i] = 0.f; g_h1[1][0][i] = 0.f;
        g_h0h[0][0][i] = zb; g_h0h[1][0][i] = zb;
        g_h0l[0][0][i] = zb; g_h0l[1][0][i] = zb;
        g_h1h[0][0][i] = zb; g_h1h[1][0][i] = zb;
        g_h1l[0][0][i] = zb; g_h1l[1][0][i] = zb;
    }
}

// ---------------- one-time: split all weights into bf16 hi/lo ----------------
__global__ void wsplit_kernel(const float* __restrict__ Wr,
                              const float* __restrict__ Wz,
                              const float* __restrict__ Wsv)
{
    int g = blockIdx.y;
    size_t i = (size_t)blockIdx.x * blockDim.x + threadIdx.x;
    const float* src = (g == 0) ? Wr : (g == 1) ? Wz : Wsv;
    bfsplit(src[i], g_Wh[g][i], g_Wl[g][i]);
}

// ---------------- shared staging: 2 stages x (A hi/lo + W hi/lo), K-chunk 32 ----------------
struct Stage {
    __nv_bfloat16 Ah[64 * LDA];
    __nv_bfloat16 Al[64 * LDA];
    __nv_bfloat16 Wh[64 * LDA];
    __nv_bfloat16 Wl[64 * LDA];
};  // 20480 B

// C[64x64] += A[64xK] * W[64xK]^T via split-bf16 mma (3 products), cp.async pipeline.
// A row stride HH; W row stride IND with k offset wk0; nk multiple of 32.
__device__ __forceinline__ void gemm_mma(
    const __nv_bfloat16* Ahg, const __nv_bfloat16* Alg,
    const __nv_bfloat16* Whg, const __nv_bfloat16* Wlg,
    int wk0, int c0, int nk,
    float (&acc)[2][4][4], Stage (&st)[2])
{
    const int tid  = threadIdx.x;
    const int lane = tid & 31;
    const int wid  = tid >> 5;
    const int wm   = (wid & 1) * 32;       // warp row base
    const int wn   = (wid >> 1) * 32;      // warp col base
    const unsigned rowB = LDA * 2;         // 80 bytes

    // per-lane ldmatrix offsets (bytes)
    const unsigned aLane = (lane & 15) * rowB + (lane >> 4) * 16;
    const unsigned bLane = (((lane >> 4) << 3) + (lane & 7)) * rowB + ((lane >> 3) & 1) * 16;

    const int nchunks = nk >> 5;

    // issue chunk `ci` into stage `s`
    auto issue = [&](int ci, int s) {
        int k0 = ci * 32;
        unsigned sAh = smem_u32(st[s].Ah), sAl = smem_u32(st[s].Al);
        unsigned sWh = smem_u32(st[s].Wh), sWl = smem_u32(st[s].Wl);
        #pragma unroll
        for (int i = 0; i < 2; ++i) {
            int q = i * 128 + tid;       // 0..255 quads
            int m = q >> 2, kq = q & 3;  // row 0..63, 16B quad 0..3
            unsigned so = (unsigned)(m * rowB + kq * 16);
            size_t  ga = (size_t)m * HH + k0 + kq * 8;
            size_t  gw = (size_t)(c0 + m) * IND + wk0 + k0 + kq * 8;
            cpa16(sAh + so, Ahg + ga);
            cpa16(sAl + so, Alg + ga);
            cpa16(sWh + so, Whg + gw);
            cpa16(sWl + so, Wlg + gw);
        }
        cpa_commit();
    };

    issue(0, 0);

    for (int ci = 0; ci < nchunks; ++ci) {
        int s = ci & 1;
        if (ci + 1 < nchunks) { issue(ci + 1, s ^ 1); cpa_wait<1>(); }
        else                  { cpa_wait<0>(); }
        __syncthreads();

        unsigned sAh = smem_u32(st[s].Ah), sAl = smem_u32(st[s].Al);
        unsigned sWh = smem_u32(st[s].Wh), sWl = smem_u32(st[s].Wl);
        #pragma unroll
        for (int kk = 0; kk < 2; ++kk) {
            unsigned ko = kk * 32;   // 16 bf16 = 32 B
            unsigned ah0[4], ah1[4], al0[4], al1[4];
            unsigned bh01[4], bh23[4], bl01[4], bl23[4];
            ldsm4(ah0, sAh + (wm     ) * rowB + aLane + ko);
            ldsm4(ah1, sAh + (wm + 16) * rowB + aLane + ko);
            ldsm4(al0, sAl + (wm     ) * rowB + aLane + ko);
            ldsm4(al1, sAl + (wm + 16) * rowB + aLane + ko);
            ldsm4(bh01, sWh + (wn     ) * rowB + bLane + ko);
            ldsm4(bh23, sWh + (wn + 16) * rowB + bLane + ko);
            ldsm4(bl01, sWl + (wn     ) * rowB + bLane + ko);
            ldsm4(bl23, sWl + (wn + 16) * rowB + bLane + ko);
            // ng0..3 B-frags: bh01+0, bh01+2, bh23+0, bh23+2 (and lo twins)
            mma_bf16(acc[0][0], ah0, bh01 + 0); mma_bf16(acc[0][0], ah0, bl01 + 0); mma_bf16(acc[0][0], al0, bh01 + 0);
            mma_bf16(acc[0][1], ah0, bh01 + 2); mma_bf16(acc[0][1], ah0, bl01 + 2); mma_bf16(acc[0][1], al0, bh01 + 2);
            mma_bf16(acc[0][2], ah0, bh23 + 0); mma_bf16(acc[0][2], ah0, bl23 + 0); mma_bf16(acc[0][2], al0, bh23 + 0);
            mma_bf16(acc[0][3], ah0, bh23 + 2); mma_bf16(acc[0][3], ah0, bl23 + 2); mma_bf16(acc[0][3], al0, bh23 + 2);
            mma_bf16(acc[1][0], ah1, bh01 + 0); mma_bf16(acc[1][0], ah1, bl01 + 0); mma_bf16(acc[1][0], al1, bh01 + 0);
            mma_bf16(acc[1][1], ah1, bh01 + 2); mma_bf16(acc[1][1], ah1, bl01 + 2); mma_bf16(acc[1][1], al1, bh01 + 2);
            mma_bf16(acc[1][2], ah1, bh23 + 0); mma_bf16(acc[1][2], ah1, bl23 + 0); mma_bf16(acc[1][2], al1, bh23 + 0);
            mma_bf16(acc[1][3], ah1, bh23 + 2); mma_bf16(acc[1][3], ah1, bl23 + 2); mma_bf16(acc[1][3], al1, bh23 + 2);
        }
        __syncthreads();
    }
}

__device__ __forceinline__ void store_acc_mma(float* dst, int c0, float (&acc)[2][4][4])
{
    int lane = threadIdx.x & 31, wid = threadIdx.x >> 5;
    int wm = (wid & 1) * 32, wn = (wid >> 1) * 32;
    int r = lane >> 2, cc = (lane & 3) * 2;
    #pragma unroll
    for (int mt = 0; mt < 2; ++mt)
        #pragma unroll
        for (int ng = 0; ng < 4; ++ng) {
            int row = wm + mt * 16 + r;
            int col = c0 + wn + ng * 8 + cc;
            *(float2*)(dst + (size_t)row * HH + col)       = make_float2(acc[mt][ng][0], acc[mt][ng][1]);
            *(float2*)(dst + (size_t)(row + 8) * HH + col) = make_float2(acc[mt][ng][2], acc[mt][ng][3]);
        }
}

// ---------------- one-time: L0 input-half preactivations, all timesteps ----------------
// grid = 6 jobs x 256 rowtiles x 8 coltiles = 12288
__global__ void __launch_bounds__(128, 2)
pre_kernel()
{
    __shared__ Stage st[2];
    int bid  = blockIdx.x;
    int job  = bid >> 11;            // 0..5
    int d    = job / 3;
    int gate = job % 3;
    int rem  = bid & 2047;
    int rowt = rem >> 3;             // 0..255
    int tile = rem & 7;              // 0..7 (N=64)

    const __nv_bfloat16* Ah = g_xh + (size_t)rowt * 64 * HH;
    const __nv_bfloat16* Al = g_xl + (size_t)rowt * 64 * HH;
    const __nv_bfloat16* Wh = g_Wh[gate] + (size_t)(d * 2 + 0) * HH * IND;
    const __nv_bfloat16* Wl = g_Wl[gate] + (size_t)(d * 2 + 0) * HH * IND;

    float acc[2][4][4] = {};
    gemm_mma(Ah, Al, Wh, Wl, 0, tile * 64, HH, acc, st);
    store_acc_mma(g_pin[d][gate] + (size_t)rowt * 64 * HH, tile * 64, acc);
}

// ---------------- the persistent recurrence kernel ----------------
// 224 blocks x 128 threads; smem 40 KB -> 5 CTAs/SM by smem, co-residency safe.
__global__ void __launch_bounds__(128, 2)
persist_kernel(const float* __restrict__ br, const float* __restrict__ bz,
               const float* __restrict__ bsv, float* __restrict__ dout)
{
    __shared__ Stage st[2];
    const int bid = blockIdx.x;
    const int tid = threadIdx.x;
    const int gtid = bid * 128 + tid;
    unsigned tgt = 0;

    for (int t = 0; t <= SQ; ++t) {
        // ============ P1: r/z GEMM slices + L1 s-input (all K=256, N=64 tiles) ============
        {
            const __nv_bfloat16 *Ah = 0, *Al = 0, *Wh = 0, *Wl = 0;
            float* dst = 0;
            int wk0 = 0, tile = 0, active = 0;
            if (bid < 64) {                         // L0 r/z recurrent: d,gate,slice(2),tile(8)
                if (t < SQ) {
                    int d     = (bid >> 5) & 1;
                    int gate  = (bid >> 4) & 1;
                    int slice = (bid >> 3) & 1;
                    tile      =  bid       & 7;
                    Ah = g_h0h[d][t & 1] + slice * 256;
                    Al = g_h0l[d][t & 1] + slice * 256;
                    Wh = g_Wh[gate] + (size_t)(d * 2 + 0) * HH * IND;
                    Wl = g_Wl[gate] + (size_t)(d * 2 + 0) * HH * IND;
                    wk0 = HH + slice * 256;
                    dst = g_paL0[d][gate][slice];
                    active = 1;
                }
            } else if (bid < 192) {                 // L1 r/z: d,gate,slice(4),tile(8)
                if (t >= 1) {
                    int q     = bid - 64;
                    int d     = (q >> 6) & 1;
                    int gate  = (q >> 5) & 1;
                    int slice = (q >> 3) & 3;
                    tile      =  q       & 7;
                    int u = t - 1;
                    if (slice < 2) {
                        Ah = g_y0h[d] + (size_t)u * BH + slice * 256;
                        Al = g_y0l[d] + (size_t)u * BH + slice * 256;
                    } else {
                        Ah = g_h1h[d][u & 1] + (slice - 2) * 256;
                        Al = g_h1l[d][u & 1] + (slice - 2) * 256;
                    }
                    Wh = g_Wh[gate] + (size_t)(d * 2 + 1) * HH * IND;
                    Wl = g_Wl[gate] + (size_t)(d * 2 + 1) * HH * IND;
                    wk0 = slice * 256;
                    dst = g_paL1[d][gate][slice];
                    active = 1;
                }
            } else {                                // L1 s-input: d,slice(2),tile(8)
                if (t >= 1) {
                    int q     = bid - 192;
                    int d     = (q >> 4) & 1;
                    int slice = (q >> 3) & 1;
                    tile      =  q       & 7;
                    int u = t - 1;
                    Ah = g_y0h[d] + (size_t)u * BH + slice * 256;
                    Al = g_y0l[d] + (size_t)u * BH + slice * 256;
                    Wh = g_Wh[2] + (size_t)(d * 2 + 1) * HH * IND;
                    Wl = g_Wl[2] + (size_t)(d * 2 + 1) * HH * IND;
                    wk0 = slice * 256;
                    dst = g_psp[d][slice];
                    active = 1;
                }
            }
            if (active) {
                float acc[2][4][4] = {};
                gemm_mma(Ah, Al, Wh, Wl, wk0, tile * 64, 256, acc, st);
                store_acc_mma(dst, tile * 64, acc);
            }
        }
        tgt += NBLK; grid_bar(tgt);

        // ============ P2: combA (r sigmoid + r*h split, z sigmoid) ============
        for (int e = gtid; e < 4 * BH; e += NBLK * 128) {
            int cell  = e >> 15;
            int layer = cell >> 1;
            int d     = cell & 1;
            if (layer == 0 && t >= SQ) continue;
            if (layer == 1 && t <  1 ) continue;
            int u   = (layer == 0) ? t : (t - 1);
            int idx = e & (BH - 1);
            int col = idx & 511;

            const float* h = (layer == 0) ? g_h0[d][u & 1] : g_h1[d][u & 1];
            float rpre, zpre;
            if (layer == 0) {
                int rt = d ? (SQ - 1 - t) : t;
                rpre = g_pin[d][0][(size_t)rt * BH + idx]
                     + g_paL0[d][0][0][idx] + g_paL0[d][0][1][idx];
                zpre = g_pin[d][1][(size_t)rt * BH + idx]
                     + g_paL0[d][1][0][idx] + g_paL0[d][1][1][idx];
            } else {
                rpre = g_paL1[d][0][0][idx] + g_paL1[d][0][1][idx]
                     + g_paL1[d][0][2][idx] + g_paL1[d][0][3][idx];
                zpre = g_paL1[d][1][0][idx] + g_paL1[d][1][1][idx]
                     + g_paL1[d][1][2][idx] + g_paL1[d][1][3][idx];
            }
            int boff = (d * 2 + layer) * HH + col;
            float rh = fsig(rpre + br[boff]) * h[idx];
            bfsplit(rh, g_rhh[layer][d][idx], g_rhl[layer][d][idx]);
            g_z[layer][d][idx] = fsig(zpre + bz[boff]);
        }
        tgt += NBLK; grid_bar(tgt);

        // ============ P3: s recurrent GEMM, K=512 in 4 slices, N=64 tiles ============
        if (bid < 128) {
            int layer = (bid >> 6) & 1;
            int d     = (bid >> 5) & 1;
            int slice = (bid >> 3) & 3;
            int tile  =  bid       & 7;
            int active = !((layer == 0 && t >= SQ) || (layer == 1 && t < 1));
            if (active) {
                const __nv_bfloat16* Ah = g_rhh[layer][d] + slice * 128;
                const __nv_bfloat16* Al = g_rhl[layer][d] + slice * 128;
                const __nv_bfloat16* Wh = g_Wh[2] + (size_t)(d * 2 + layer) * HH * IND;
                const __nv_bfloat16* Wl = g_Wl[2] + (size_t)(d * 2 + layer) * HH * IND;
                float acc[2][4][4] = {};
                gemm_mma(Ah, Al, Wh, Wl, HH + slice * 128, tile * 64, 128, acc, st);
                store_acc_mma(g_sp[layer][d][slice], tile * 64, acc);
            }
        }
        tgt += NBLK; grid_bar(tgt);

        // ============ P4: combS (tanh + mix + h update + splits + outputs) ============
        for (int e = gtid; e < 4 * BH; e += NBLK * 128) {
            int cell  = e >> 15;
            int layer = cell >> 1;
            int d     = cell & 1;
            if (layer == 0 && t >= SQ) continue;
            if (layer == 1 && t <  1 ) continue;
            int u   = (layer == 0) ? t : (t - 1);
            int idx = e & (BH - 1);
            int m   = idx >> 9;
            int col = idx & 511;

            float pre;
            if (layer == 0) {
                int rt = d ? (SQ - 1 - t) : t;
                pre = g_pin[d][2][(size_t)rt * BH + idx];
            } else {
                pre = g_psp[d][0][idx] + g_psp[d][1][idx];
            }
            pre += bsv[(d * 2 + layer) * HH + col];
            pre += g_sp[layer][d][0][idx] + g_sp[layer][d][1][idx]
                 + g_sp[layer][d][2][idx] + g_sp[layer][d][3][idx];

            float s = tanhf(pre);
            float z = g_z[layer][d][idx];

            const float* hp = (layer == 0) ? g_h0[d][u & 1]       : g_h1[d][u & 1];
            float*       hn = (layer == 0) ? g_h0[d][(u + 1) & 1] : g_h1[d][(u + 1) & 1];

            float h = z * hp[idx] + (1.f - z) * s;
            hn[idx] = h;
            if (layer == 0) {
                bfsplit(h, g_h0h[d][(u + 1) & 1][idx], g_h0l[d][(u + 1) & 1][idx]);
                bfsplit(h, g_y0h[d][(size_t)u * BH + idx], g_y0l[d][(size_t)u * BH + idx]);
                if (u == SQ - 1)
                    dout[OUT_SZ + (size_t)(d * 2 + 0) * BH + idx] = h;
            } else {
                bfsplit(h, g_h1h[d][(u + 1) & 1][idx], g_h1l[d][(u + 1) & 1][idx]);
                dout[(size_t)u * BB * (2 * HH) + (size_t)m * (2 * HH) + d * HH + col] = h;
                if (u == SQ - 1)
                    dout[OUT_SZ + (size_t)(d * 2 + 1) * BH + idx] = h;
            }
        }
        tgt += NBLK; grid_bar(tgt);
    }
}

// ---------------- launcher: 5 graph nodes ----------------
extern "C" void kernel_launch(void* const* d_in, const int* in_sizes, int n_in,
                              void* d_out, int out_size)
{
    const int*   tok = (const int*)  d_in[0];
    const float* emb = (const float*)d_in[1];
    const float* Wr  = (const float*)d_in[2];
    const float* Wz  = (const float*)d_in[3];
    const float* Wsv = (const float*)d_in[4];
    const float* br  = (const float*)d_in[5];
    const float* bz  = (const float*)d_in[6];
    const float* bsv = (const float*)d_in[7];
    float* outp = (float*)d_out;

    embed_kernel<<<SQ * BB, 128>>>(tok, emb);
    init_kernel<<<(BH + 255) / 256, 256>>>();
    {
        dim3 g((4 * HH * IND) / 256, 3);
        wsplit_kernel<<<g, 256>>>(Wr, Wz, Wsv);
    }
    pre_kernel<<<12288, 128>>>();
    persist_kernel<<<NBLK, 128>>>(br, bz, bsv, outp);
}

// round 16
// speedup vs baseline: 1.1553x; 1.1553x over previous
#include <cuda_runtime.h>
#include <cuda_bf16.h>
#include <math.h>

// Problem constants
#define SQ   256
#define BB   64
#define HH   512
#define IND  1024
#define BH   (BB*HH)      // 32768
#define SBH  (SQ*BB*HH)   // 8388608
#define OUT_SZ ((size_t)SQ*BB*2*HH)
#define NBLK 448          // persistent grid size
#define LDA  40           // bf16 per smem row (80 B): conflict-free ldmatrix

// ---------------- fp32 scratch ----------------
__device__ float g_h0 [2][2][BH];       // layer-0 hidden ping-pong [dir][parity]
__device__ float g_h1 [2][2][BH];       // layer-1 hidden ping-pong
__device__ float g_z  [2][2][BH];       // z gate
__device__ float g_pin[2][3][SBH];      // precomputed L0 input-half preact [d][gate]
__device__ float g_paL0[2][2][4][BH];   // L0 r/z recurrent partials [d][gate][slice K=128]
__device__ float g_paL1[2][2][8][BH];   // L1 r/z partials [d][gate][slice K=128]
__device__ float g_psp [2][4][BH];      // L1 s-input partials [d][slice K=128]
__device__ float g_sp  [2][2][8][BH];   // s recurrent partials [layer][d][slice K=64]
__device__ unsigned g_bar;              // grid barrier counter

// ---------------- bf16 split operands (hi + lo) ----------------
__device__ __align__(16) __nv_bfloat16 g_xh [SBH],        g_xl [SBH];
__device__ __align__(16) __nv_bfloat16 g_y0h[2][SBH],     g_y0l[2][SBH];
__device__ __align__(16) __nv_bfloat16 g_h0h[2][2][BH],   g_h0l[2][2][BH];
__device__ __align__(16) __nv_bfloat16 g_h1h[2][2][BH],   g_h1l[2][2][BH];
__device__ __align__(16) __nv_bfloat16 g_rhh[2][2][BH],   g_rhl[2][2][BH];
__device__ __align__(16) __nv_bfloat16 g_Wh[3][4*HH*IND], g_Wl[3][4*HH*IND]; // [gate r/z/s]

__device__ __forceinline__ float fsig(float x) { return 1.f / (1.f + __expf(-x)); }

__device__ __forceinline__ void bfsplit(float x, __nv_bfloat16& h, __nv_bfloat16& l)
{
    h = __float2bfloat16(x);
    l = __float2bfloat16(x - __bfloat162float(h));
}

__device__ __forceinline__ unsigned smem_u32(const void* p)
{
    return (unsigned)__cvta_generic_to_shared(p);
}

// ---------------- mma / ldmatrix / cp.async wrappers ----------------
__device__ __forceinline__ void mma_bf16(float* c, const unsigned* a, const unsigned* b)
{
    asm volatile(
        "mma.sync.aligned.m16n8k16.row.col.f32.bf16.bf16.f32 "
        "{%0,%1,%2,%3},{%4,%5,%6,%7},{%8,%9},{%0,%1,%2,%3};\n"
        : "+f"(c[0]), "+f"(c[1]), "+f"(c[2]), "+f"(c[3])
        : "r"(a[0]), "r"(a[1]), "r"(a[2]), "r"(a[3]), "r"(b[0]), "r"(b[1]));
}
__device__ __forceinline__ void ldsm4(unsigned* r, unsigned addr)
{
    asm volatile("ldmatrix.sync.aligned.m8n8.x4.shared.b16 {%0,%1,%2,%3},[%4];\n"
        : "=r"(r[0]), "=r"(r[1]), "=r"(r[2]), "=r"(r[3]) : "r"(addr));
}
__device__ __forceinline__ void cpa16(unsigned s, const void* g)
{
    asm volatile("cp.async.cg.shared.global [%0], [%1], 16;\n" :: "r"(s), "l"(g));
}
__device__ __forceinline__ void cpa_commit()
{
    asm volatile("cp.async.commit_group;\n");
}
template<int N> __device__ __forceinline__ void cpa_wait()
{
    asm volatile("cp.async.wait_group %0;\n" :: "n"(N));
}

// ---------------- grid-wide spin barrier ----------------
__device__ __forceinline__ void grid_bar(unsigned target)
{
    __threadfence();
    __syncthreads();
    if (threadIdx.x == 0) {
        atomicAdd(&g_bar, 1u);
        while (atomicAdd(&g_bar, 0u) < target)
            __nanosleep(64);
        __threadfence();   // acquire + L1 invalidate
    }
    __syncthreads();
}

// ---------------- embedding gather: write split x, reset barrier ----------------
__global__ void embed_kernel(const int* __restrict__ tok,
                             const float* __restrict__ emb)
{
    if (blockIdx.x == 0 && threadIdx.x == 0) g_bar = 0u;
    int row = blockIdx.x;
    int t = tok[row];
    float4 v = ((const float4*)(emb + (size_t)t * HH))[threadIdx.x];
    size_t base = (size_t)row * HH + threadIdx.x * 4;
    float xs[4] = {v.x, v.y, v.z, v.w};
    #pragma unroll
    for (int j = 0; j < 4; ++j)
        bfsplit(xs[j], g_xh[base + j], g_xl[base + j]);
}

__global__ void init_kernel()
{
    int i = blockIdx.x * blockDim.x + threadIdx.x;
    if (i < BH) {
        __nv_bfloat16 zb = __float2bfloat16(0.f);
        g_h0[0][0][i] = 0.f; g_h0[1][0][i] = 0.f;
        g_h1[0][0][i] = 0.f; g_h1[1][0][i] = 0.f;
        g_h0h[0][0][i] = zb; g_h0h[1][0][i] = zb;
        g_h0l[0][0][i] = zb; g_h0l[1][0][i] = zb;
        g_h1h[0][0][i] = zb; g_h1h[1][0][i] = zb;
        g_h1l[0][0][i] = zb; g_h1l[1][0][i] = zb;
    }
}

// ---------------- one-time: split all weights into bf16 hi/lo ----------------
__global__ void wsplit_kernel(const float* __restrict__ Wr,
                              const float* __restrict__ Wz,
                              const float* __restrict__ Wsv)
{
    int g = blockIdx.y;
    size_t i = (size_t)blockIdx.x * blockDim.x + threadIdx.x;
    const float* src = (g == 0) ? Wr : (g == 1) ? Wz : Wsv;
    bfsplit(src[i], g_Wh[g][i], g_Wl[g][i]);
}

// ---------------- shared staging: 2 stages x (A hi/lo + W hi/lo), K-chunk 32 ----------------
struct Stage {
    __nv_bfloat16 Ah[64 * LDA];
    __nv_bfloat16 Al[64 * LDA];
    __nv_bfloat16 Wh[64 * LDA];
    __nv_bfloat16 Wl[64 * LDA];
};  // 20480 B

// C[64x64] += A[64xK] * W[64xK]^T via split-bf16 mma (3 products), cp.async pipeline.
// A row stride HH; W row stride IND with k offset wk0; nk multiple of 32.
__device__ __forceinline__ void gemm_mma(
    const __nv_bfloat16* Ahg, const __nv_bfloat16* Alg,
    const __nv_bfloat16* Whg, const __nv_bfloat16* Wlg,
    int wk0, int c0, int nk,
    float (&acc)[2][4][4], Stage (&st)[2])
{
    const int tid  = threadIdx.x;
    const int lane = tid & 31;
    const int wid  = tid >> 5;
    const int wm   = (wid & 1) * 32;       // warp row base
    const int wn   = (wid >> 1) * 32;      // warp col base
    const unsigned rowB = LDA * 2;         // 80 bytes

    const unsigned aLane = (lane & 15) * rowB + (lane >> 4) * 16;
    const unsigned bLane = (((lane >> 4) << 3) + (lane & 7)) * rowB + ((lane >> 3) & 1) * 16;

    const int nchunks = nk >> 5;

    auto issue = [&](int ci, int s) {
        int k0 = ci * 32;
        unsigned sAh = smem_u32(st[s].Ah), sAl = smem_u32(st[s].Al);
        unsigned sWh = smem_u32(st[s].Wh), sWl = smem_u32(st[s].Wl);
        #pragma unroll
        for (int i = 0; i < 2; ++i) {
            int q = i * 128 + tid;
            int m = q >> 2, kq = q & 3;
            unsigned so = (unsigned)(m * rowB + kq * 16);
            size_t  ga = (size_t)m * HH + k0 + kq * 8;
            size_t  gw = (size_t)(c0 + m) * IND + wk0 + k0 + kq * 8;
            cpa16(sAh + so, Ahg + ga);
            cpa16(sAl + so, Alg + ga);
            cpa16(sWh + so, Whg + gw);
            cpa16(sWl + so, Wlg + gw);
        }
        cpa_commit();
    };

    issue(0, 0);

    for (int ci = 0; ci < nchunks; ++ci) {
        int s = ci & 1;
        if (ci + 1 < nchunks) { issue(ci + 1, s ^ 1); cpa_wait<1>(); }
        else                  { cpa_wait<0>(); }
        __syncthreads();

        unsigned sAh = smem_u32(st[s].Ah), sAl = smem_u32(st[s].Al);
        unsigned sWh = smem_u32(st[s].Wh), sWl = smem_u32(st[s].Wl);
        #pragma unroll
        for (int kk = 0; kk < 2; ++kk) {
            unsigned ko = kk * 32;
            unsigned ah0[4], ah1[4], al0[4], al1[4];
            unsigned bh01[4], bh23[4], bl01[4], bl23[4];
            ldsm4(ah0, sAh + (wm     ) * rowB + aLane + ko);
            ldsm4(ah1, sAh + (wm + 16) * rowB + aLane + ko);
            ldsm4(al0, sAl + (wm     ) * rowB + aLane + ko);
            ldsm4(al1, sAl + (wm + 16) * rowB + aLane + ko);
            ldsm4(bh01, sWh + (wn     ) * rowB + bLane + ko);
            ldsm4(bh23, sWh + (wn + 16) * rowB + bLane + ko);
            ldsm4(bl01, sWl + (wn     ) * rowB + bLane + ko);
            ldsm4(bl23, sWl + (wn + 16) * rowB + bLane + ko);
            mma_bf16(acc[0][0], ah0, bh01 + 0); mma_bf16(acc[0][0], ah0, bl01 + 0); mma_bf16(acc[0][0], al0, bh01 + 0);
            mma_bf16(acc[0][1], ah0, bh01 + 2); mma_bf16(acc[0][1], ah0, bl01 + 2); mma_bf16(acc[0][1], al0, bh01 + 2);
            mma_bf16(acc[0][2], ah0, bh23 + 0); mma_bf16(acc[0][2], ah0, bl23 + 0); mma_bf16(acc[0][2], al0, bh23 + 0);
            mma_bf16(acc[0][3], ah0, bh23 + 2); mma_bf16(acc[0][3], ah0, bl23 + 2); mma_bf16(acc[0][3], al0, bh23 + 2);
            mma_bf16(acc[1][0], ah1, bh01 + 0); mma_bf16(acc[1][0], ah1, bl01 + 0); mma_bf16(acc[1][0], al1, bh01 + 0);
            mma_bf16(acc[1][1], ah1, bh01 + 2); mma_bf16(acc[1][1], ah1, bl01 + 2); mma_bf16(acc[1][1], al1, bh01 + 2);
            mma_bf16(acc[1][2], ah1, bh23 + 0); mma_bf16(acc[1][2], ah1, bl23 + 0); mma_bf16(acc[1][2], al1, bh23 + 0);
            mma_bf16(acc[1][3], ah1, bh23 + 2); mma_bf16(acc[1][3], ah1, bl23 + 2); mma_bf16(acc[1][3], al1, bh23 + 2);
        }
        __syncthreads();
    }
}

__device__ __forceinline__ void store_acc_mma(float* dst, int c0, float (&acc)[2][4][4])
{
    int lane = threadIdx.x & 31, wid = threadIdx.x >> 5;
    int wm = (wid & 1) * 32, wn = (wid >> 1) * 32;
    int r = lane >> 2, cc = (lane & 3) * 2;
    #pragma unroll
    for (int mt = 0; mt < 2; ++mt)
        #pragma unroll
        for (int ng = 0; ng < 4; ++ng) {
            int row = wm + mt * 16 + r;
            int col = c0 + wn + ng * 8 + cc;
            *(float2*)(dst + (size_t)row * HH + col)       = make_float2(acc[mt][ng][0], acc[mt][ng][1]);
            *(float2*)(dst + (size_t)(row + 8) * HH + col) = make_float2(acc[mt][ng][2], acc[mt][ng][3]);
        }
}

// ---------------- one-time: L0 input-half preactivations, all timesteps ----------------
__global__ void __launch_bounds__(128, 2)
pre_kernel()
{
    __shared__ Stage st[2];
    int bid  = blockIdx.x;
    int job  = bid >> 11;            // 0..5
    int d    = job / 3;
    int gate = job % 3;
    int rem  = bid & 2047;
    int rowt = rem >> 3;             // 0..255
    int tile = rem & 7;              // 0..7

    const __nv_bfloat16* Ah = g_xh + (size_t)rowt * 64 * HH;
    const __nv_bfloat16* Al = g_xl + (size_t)rowt * 64 * HH;
    const __nv_bfloat16* Wh = g_Wh[gate] + (size_t)(d * 2 + 0) * HH * IND;
    const __nv_bfloat16* Wl = g_Wl[gate] + (size_t)(d * 2 + 0) * HH * IND;

    float acc[2][4][4] = {};
    gemm_mma(Ah, Al, Wh, Wl, 0, tile * 64, HH, acc, st);
    store_acc_mma(g_pin[d][gate] + (size_t)rowt * 64 * HH, tile * 64, acc);
}

// ---------------- the persistent recurrence kernel ----------------
// 448 blocks x 128 threads; 41 KB smem/CTA, regs capped 128 -> 4 CTAs/SM
// guaranteed residency (448 <= 592), ~3 CTAs/SM for latency overlap.
__global__ void __launch_bounds__(128, 4)
persist_kernel(const float* __restrict__ br, const float* __restrict__ bz,
               const float* __restrict__ bsv, float* __restrict__ dout)
{
    __shared__ Stage st[2];
    const int bid = blockIdx.x;
    const int tid = threadIdx.x;
    const int gtid = bid * 128 + tid;
    unsigned tgt = 0;

    for (int t = 0; t <= SQ; ++t) {
        // ============ P1: r/z GEMM slices + L1 s-input (all K=128, N=64 tiles) ============
        {
            const __nv_bfloat16 *Ah = 0, *Al = 0, *Wh = 0, *Wl = 0;
            float* dst = 0;
            int wk0 = 0, tile = 0, active = 0;
            if (bid < 128) {                        // L0 r/z: d,gate,slice(4),tile(8)
                if (t < SQ) {
                    int d     = (bid >> 6) & 1;
                    int gate  = (bid >> 5) & 1;
                    int slice = (bid >> 3) & 3;
                    tile      =  bid       & 7;
                    Ah = g_h0h[d][t & 1] + slice * 128;
                    Al = g_h0l[d][t & 1] + slice * 128;
                    Wh = g_Wh[gate] + (size_t)(d * 2 + 0) * HH * IND;
                    Wl = g_Wl[gate] + (size_t)(d * 2 + 0) * HH * IND;
                    wk0 = HH + slice * 128;
                    dst = g_paL0[d][gate][slice];
                    active = 1;
                }
            } else if (bid < 384) {                 // L1 r/z: d,gate,slice(8),tile(8)
                if (t >= 1) {
                    int q     = bid - 128;
                    int d     = (q >> 7) & 1;
                    int gate  = (q >> 6) & 1;
                    int slice = (q >> 3) & 7;
                    tile      =  q       & 7;
                    int u = t - 1;
                    if (slice < 4) {
                        Ah = g_y0h[d] + (size_t)u * BH + slice * 128;
                        Al = g_y0l[d] + (size_t)u * BH + slice * 128;
                    } else {
                        Ah = g_h1h[d][u & 1] + (slice - 4) * 128;
                        Al = g_h1l[d][u & 1] + (slice - 4) * 128;
                    }
                    Wh = g_Wh[gate] + (size_t)(d * 2 + 1) * HH * IND;
                    Wl = g_Wl[gate] + (size_t)(d * 2 + 1) * HH * IND;
                    wk0 = slice * 128;
                    dst = g_paL1[d][gate][slice];
                    active = 1;
                }
            } else {                                // L1 s-input: d,slice(4),tile(8)
                if (t >= 1) {
                    int q     = bid - 384;
                    int d     = (q >> 5) & 1;
                    int slice = (q >> 3) & 3;
                    tile      =  q       & 7;
                    int u = t - 1;
                    Ah = g_y0h[d] + (size_t)u * BH + slice * 128;
                    Al = g_y0l[d] + (size_t)u * BH + slice * 128;
                    Wh = g_Wh[2] + (size_t)(d * 2 + 1) * HH * IND;
                    Wl = g_Wl[2] + (size_t)(d * 2 + 1) * HH * IND;
                    wk0 = slice * 128;
                    dst = g_psp[d][slice];
                    active = 1;
                }
            }
            if (active) {
                float acc[2][4][4] = {};
                gemm_mma(Ah, Al, Wh, Wl, wk0, tile * 64, 128, acc, st);
                store_acc_mma(dst, tile * 64, acc);
            }
        }
        tgt += NBLK; grid_bar(tgt);

        // ============ P2: combA (r sigmoid + r*h split, z sigmoid) ============
        for (int e = gtid; e < 4 * BH; e += NBLK * 128) {
            int cell  = e >> 15;
            int layer = cell >> 1;
            int d     = cell & 1;
            if (layer == 0 && t >= SQ) continue;
            if (layer == 1 && t <  1 ) continue;
            int u   = (layer == 0) ? t : (t - 1);
            int idx = e & (BH - 1);
            int col = idx & 511;

            const float* h = (layer == 0) ? g_h0[d][u & 1] : g_h1[d][u & 1];
            float rpre, zpre;
            if (layer == 0) {
                int rt = d ? (SQ - 1 - t) : t;
                rpre = g_pin[d][0][(size_t)rt * BH + idx]
                     + g_paL0[d][0][0][idx] + g_paL0[d][0][1][idx]
                     + g_paL0[d][0][2][idx] + g_paL0[d][0][3][idx];
                zpre = g_pin[d][1][(size_t)rt * BH + idx]
                     + g_paL0[d][1][0][idx] + g_paL0[d][1][1][idx]
                     + g_paL0[d][1][2][idx] + g_paL0[d][1][3][idx];
            } else {
                rpre = zpre = 0.f;
                #pragma unroll
                for (int sl = 0; sl < 8; ++sl) {
                    rpre += g_paL1[d][0][sl][idx];
                    zpre += g_paL1[d][1][sl][idx];
                }
            }
            int boff = (d * 2 + layer) * HH + col;
            float rh = fsig(rpre + br[boff]) * h[idx];
            bfsplit(rh, g_rhh[layer][d][idx], g_rhl[layer][d][idx]);
            g_z[layer][d][idx] = fsig(zpre + bz[boff]);
        }
        tgt += NBLK; grid_bar(tgt);

        // ============ P3: s recurrent GEMM, K=512 in 8 slices of 64 ============
        if (bid < 256) {
            int layer = (bid >> 7) & 1;
            int d     = (bid >> 6) & 1;
            int slice = (bid >> 3) & 7;
            int tile  =  bid       & 7;
            int active = !((layer == 0 && t >= SQ) || (layer == 1 && t < 1));
            if (active) {
                const __nv_bfloat16* Ah = g_rhh[layer][d] + slice * 64;
                const __nv_bfloat16* Al = g_rhl[layer][d] + slice * 64;
                const __nv_bfloat16* Wh = g_Wh[2] + (size_t)(d * 2 + layer) * HH * IND;
                const __nv_bfloat16* Wl = g_Wl[2] + (size_t)(d * 2 + layer) * HH * IND;
                float acc[2][4][4] = {};
                gemm_mma(Ah, Al, Wh, Wl, HH + slice * 64, tile * 64, 64, acc, st);
                store_acc_mma(g_sp[layer][d][slice], tile * 64, acc);
            }
        }
        tgt += NBLK; grid_bar(tgt);

        // ============ P4: combS (tanh + mix + h update + splits + outputs) ============
        for (int e = gtid; e < 4 * BH; e += NBLK * 128) {
            int cell  = e >> 15;
            int layer = cell >> 1;
            int d     = cell & 1;
            if (layer == 0 && t >= SQ) continue;
            if (layer == 1 && t <  1 ) continue;
            int u   = (layer == 0) ? t : (t - 1);
            int idx = e & (BH - 1);
            int m   = idx >> 9;
            int col = idx & 511;

            float pre;
            if (layer == 0) {
                int rt = d ? (SQ - 1 - t) : t;
                pre = g_pin[d][2][(size_t)rt * BH + idx];
            } else {
                pre = g_psp[d][0][idx] + g_psp[d][1][idx]
                    + g_psp[d][2][idx] + g_psp[d][3][idx];
            }
            pre += bsv[(d * 2 + layer) * HH + col];
            #pragma unroll
            for (int sl = 0; sl < 8; ++sl)
                pre += g_sp[layer][d][sl][idx];

            float s = tanhf(pre);
            float z = g_z[layer][d][idx];

            const float* hp = (layer == 0) ? g_h0[d][u & 1]       : g_h1[d][u & 1];
            float*       hn = (layer == 0) ? g_h0[d][(u + 1) & 1] : g_h1[d][(u + 1) & 1];

            float h = z * hp[idx] + (1.f - z) * s;
            hn[idx] = h;
            if (layer == 0) {
                bfsplit(h, g_h0h[d][(u + 1) & 1][idx], g_h0l[d][(u + 1) & 1][idx]);
                bfsplit(h, g_y0h[d][(size_t)u * BH + idx], g_y0l[d][(size_t)u * BH + idx]);
                if (u == SQ - 1)
                    dout[OUT_SZ + (size_t)(d * 2 + 0) * BH + idx] = h;
            } else {
                bfsplit(h, g_h1h[d][(u + 1) & 1][idx], g_h1l[d][(u + 1) & 1][idx]);
                dout[(size_t)u * BB * (2 * HH) + (size_t)m * (2 * HH) + d * HH + col] = h;
                if (u == SQ - 1)
                    dout[OUT_SZ + (size_t)(d * 2 + 1) * BH + idx] = h;
            }
        }
        tgt += NBLK; grid_bar(tgt);
    }
}

// ---------------- launcher: 5 graph nodes ----------------
extern "C" void kernel_launch(void* const* d_in, const int* in_sizes, int n_in,
                              void* d_out, int out_size)
{
    const int*   tok = (const int*)  d_in[0];
    const float* emb = (const float*)d_in[1];
    const float* Wr  = (const float*)d_in[2];
    const float* Wz  = (const float*)d_in[3];
    const float* Wsv = (const float*)d_in[4];
    const float* br  = (const float*)d_in[5];
    const float* bz  = (const float*)d_in[6];
    const float* bsv = (const float*)d_in[7];
    float* outp = (float*)d_out;

    embed_kernel<<<SQ * BB, 128>>>(tok, emb);
    init_kernel<<<(BH + 255) / 256, 256>>>();
    {
        dim3 g((4 * HH * IND) / 256, 3);
        wsplit_kernel<<<g, 256>>>(Wr, Wz, Wsv);
    }
    pre_kernel<<<12288, 128>>>();
    persist_kernel<<<NBLK, 128>>>(br, bz, bsv, outp);
}

// round 17
// speedup vs baseline: 1.2335x; 1.0677x over previous
#include <cuda_runtime.h>
#include <cuda_bf16.h>
#include <math.h>

// Problem constants
#define SQ   256
#define BB   64
#define HH   512
#define IND  1024
#define BH   (BB*HH)      // 32768
#define SBH  (SQ*BB*HH)   // 8388608
#define OUT_SZ ((size_t)SQ*BB*2*HH)
#define NBLK 448          // persistent grid size
#define LDA  40           // bf16 per smem row (80 B): conflict-free ldmatrix

// ---------------- fp32 scratch ----------------
__device__ float g_h0 [2][2][BH];       // layer-0 hidden ping-pong [dir][parity]
__device__ float g_h1 [2][2][BH];       // layer-1 hidden ping-pong
__device__ float g_z  [2][2][BH];       // z gate
__device__ float g_pin[2][3][SBH];      // precomputed L0 input-half preact [d][gate]
__device__ float g_paL0[2][2][4][BH];   // L0 r/z recurrent partials [d][gate][slice K=128]
__device__ float g_paL1[2][2][8][BH];   // L1 r/z partials [d][gate][slice K=128]
__device__ float g_psp [2][4][BH];      // L1 s-input partials [d][slice K=128]
__device__ float g_sp  [2][2][8][BH];   // s recurrent partials [layer][d][slice K=64]
__device__ unsigned g_bar;              // grid barrier counter

// ---------------- bf16 split operands (hi + lo) ----------------
__device__ __align__(16) __nv_bfloat16 g_xh [SBH],        g_xl [SBH];
__device__ __align__(16) __nv_bfloat16 g_y0h[2][SBH],     g_y0l[2][SBH];
__device__ __align__(16) __nv_bfloat16 g_h0h[2][2][BH],   g_h0l[2][2][BH];
__device__ __align__(16) __nv_bfloat16 g_h1h[2][2][BH],   g_h1l[2][2][BH];
__device__ __align__(16) __nv_bfloat16 g_rhh[2][2][BH],   g_rhl[2][2][BH];
__device__ __align__(16) __nv_bfloat16 g_Wh[3][4*HH*IND], g_Wl[3][4*HH*IND]; // [gate r/z/s]

__device__ __forceinline__ float fsig(float x) { return 1.f / (1.f + __expf(-x)); }

__device__ __forceinline__ void bfsplit(float x, __nv_bfloat16& h, __nv_bfloat16& l)
{
    h = __float2bfloat16(x);
    l = __float2bfloat16(x - __bfloat162float(h));
}

__device__ __forceinline__ unsigned smem_u32(const void* p)
{
    return (unsigned)__cvta_generic_to_shared(p);
}

// ---------------- mma / ldmatrix / cp.async wrappers ----------------
__device__ __forceinline__ void mma_bf16(float* c, const unsigned* a, const unsigned* b)
{
    asm volatile(
        "mma.sync.aligned.m16n8k16.row.col.f32.bf16.bf16.f32 "
        "{%0,%1,%2,%3},{%4,%5,%6,%7},{%8,%9},{%0,%1,%2,%3};\n"
        : "+f"(c[0]), "+f"(c[1]), "+f"(c[2]), "+f"(c[3])
        : "r"(a[0]), "r"(a[1]), "r"(a[2]), "r"(a[3]), "r"(b[0]), "r"(b[1]));
}
__device__ __forceinline__ void ldsm4(unsigned* r, unsigned addr)
{
    asm volatile("ldmatrix.sync.aligned.m8n8.x4.shared.b16 {%0,%1,%2,%3},[%4];\n"
        : "=r"(r[0]), "=r"(r[1]), "=r"(r[2]), "=r"(r[3]) : "r"(addr));
}
__device__ __forceinline__ void cpa16(unsigned s, const void* g)
{
    asm volatile("cp.async.cg.shared.global [%0], [%1], 16;\n" :: "r"(s), "l"(g));
}
__device__ __forceinline__ void cpa_commit()
{
    asm volatile("cp.async.commit_group;\n");
}
template<int N> __device__ __forceinline__ void cpa_wait()
{
    asm volatile("cp.async.wait_group %0;\n" :: "n"(N));
}

// ---------------- grid-wide barrier (cooperative-groups pattern) ----------------
// bar.sync makes all block threads' prior writes visible to tid0 (cumulativity);
// tid0's red.release publishes them GPU-wide; tid0's ld.acquire spin observes the
// other blocks' releases (and provides the L1-invalidate acquire semantics);
// the trailing bar.sync extends the acquire to all block threads.
__device__ __forceinline__ void grid_bar(unsigned target)
{
    __syncthreads();
    if (threadIdx.x == 0) {
        unsigned* p = &g_bar;
        asm volatile("red.release.gpu.add.u32 [%0], 1;" :: "l"(p) : "memory");
        unsigned v;
        do {
            asm volatile("ld.acquire.gpu.u32 %0, [%1];" : "=r"(v) : "l"(p) : "memory");
        } while (v < target);
    }
    __syncthreads();
}

// ---------------- embedding gather: write split x, reset barrier ----------------
__global__ void embed_kernel(const int* __restrict__ tok,
                             const float* __restrict__ emb)
{
    if (blockIdx.x == 0 && threadIdx.x == 0) g_bar = 0u;
    int row = blockIdx.x;
    int t = tok[row];
    float4 v = ((const float4*)(emb + (size_t)t * HH))[threadIdx.x];
    size_t base = (size_t)row * HH + threadIdx.x * 4;
    float xs[4] = {v.x, v.y, v.z, v.w};
    #pragma unroll
    for (int j = 0; j < 4; ++j)
        bfsplit(xs[j], g_xh[base + j], g_xl[base + j]);
}

__global__ void init_kernel()
{
    int i = blockIdx.x * blockDim.x + threadIdx.x;
    if (i < BH) {
        __nv_bfloat16 zb = __float2bfloat16(0.f);
        g_h0[0][0][i] = 0.f; g_h0[1][0][i] = 0.f;
        g_h1[0][0][i] = 0.f; g_h1[1][0][i] = 0.f;
        g_h0h[0][0][i] = zb; g_h0h[1][0][i] = zb;
        g_h0l[0][0][i] = zb; g_h0l[1][0][i] = zb;
        g_h1h[0][0][i] = zb; g_h1h[1][0][i] = zb;
        g_h1l[0][0][i] = zb; g_h1l[1][0][i] = zb;
    }
}

// ---------------- one-time: split all weights into bf16 hi/lo ----------------
__global__ void wsplit_kernel(const float* __restrict__ Wr,
                              const float* __restrict__ Wz,
                              const float* __restrict__ Wsv)
{
    int g = blockIdx.y;
    size_t i = (size_t)blockIdx.x * blockDim.x + threadIdx.x;
    const float* src = (g == 0) ? Wr : (g == 1) ? Wz : Wsv;
    bfsplit(src[i], g_Wh[g][i], g_Wl[g][i]);
}

// ---------------- shared staging: 2 stages x (A hi/lo + W hi/lo), K-chunk 32 ----------------
struct Stage {
    __nv_bfloat16 Ah[64 * LDA];
    __nv_bfloat16 Al[64 * LDA];
    __nv_bfloat16 Wh[64 * LDA];
    __nv_bfloat16 Wl[64 * LDA];
};  // 20480 B

// C[64x64] += A[64xK] * W[64xK]^T via split-bf16 mma (3 products), cp.async pipeline.
// A row stride HH; W row stride IND with k offset wk0; nk multiple of 32.
__device__ __forceinline__ void gemm_mma(
    const __nv_bfloat16* Ahg, const __nv_bfloat16* Alg,
    const __nv_bfloat16* Whg, const __nv_bfloat16* Wlg,
    int wk0, int c0, int nk,
    float (&acc)[2][4][4], Stage (&st)[2])
{
    const int tid  = threadIdx.x;
    const int lane = tid & 31;
    const int wid  = tid >> 5;
    const int wm   = (wid & 1) * 32;       // warp row base
    const int wn   = (wid >> 1) * 32;      // warp col base
    const unsigned rowB = LDA * 2;         // 80 bytes

    const unsigned aLane = (lane & 15) * rowB + (lane >> 4) * 16;
    const unsigned bLane = (((lane >> 4) << 3) + (lane & 7)) * rowB + ((lane >> 3) & 1) * 16;

    const int nchunks = nk >> 5;

    auto issue = [&](int ci, int s) {
        int k0 = ci * 32;
        unsigned sAh = smem_u32(st[s].Ah), sAl = smem_u32(st[s].Al);
        unsigned sWh = smem_u32(st[s].Wh), sWl = smem_u32(st[s].Wl);
        #pragma unroll
        for (int i = 0; i < 2; ++i) {
            int q = i * 128 + tid;
            int m = q >> 2, kq = q & 3;
            unsigned so = (unsigned)(m * rowB + kq * 16);
            size_t  ga = (size_t)m * HH + k0 + kq * 8;
            size_t  gw = (size_t)(c0 + m) * IND + wk0 + k0 + kq * 8;
            cpa16(sAh + so, Ahg + ga);
            cpa16(sAl + so, Alg + ga);
            cpa16(sWh + so, Whg + gw);
            cpa16(sWl + so, Wlg + gw);
        }
        cpa_commit();
    };

    issue(0, 0);

    for (int ci = 0; ci < nchunks; ++ci) {
        int s = ci & 1;
        if (ci + 1 < nchunks) { issue(ci + 1, s ^ 1); cpa_wait<1>(); }
        else                  { cpa_wait<0>(); }
        __syncthreads();

        unsigned sAh = smem_u32(st[s].Ah), sAl = smem_u32(st[s].Al);
        unsigned sWh = smem_u32(st[s].Wh), sWl = smem_u32(st[s].Wl);
        #pragma unroll
        for (int kk = 0; kk < 2; ++kk) {
            unsigned ko = kk * 32;
            unsigned ah0[4], ah1[4], al0[4], al1[4];
            unsigned bh01[4], bh23[4], bl01[4], bl23[4];
            ldsm4(ah0, sAh + (wm     ) * rowB + aLane + ko);
            ldsm4(ah1, sAh + (wm + 16) * rowB + aLane + ko);
            ldsm4(al0, sAl + (wm     ) * rowB + aLane + ko);
            ldsm4(al1, sAl + (wm + 16) * rowB + aLane + ko);
            ldsm4(bh01, sWh + (wn     ) * rowB + bLane + ko);
            ldsm4(bh23, sWh + (wn + 16) * rowB + bLane + ko);
            ldsm4(bl01, sWl + (wn     ) * rowB + bLane + ko);
            ldsm4(bl23, sWl + (wn + 16) * rowB + bLane + ko);
            mma_bf16(acc[0][0], ah0, bh01 + 0); mma_bf16(acc[0][0], ah0, bl01 + 0); mma_bf16(acc[0][0], al0, bh01 + 0);
            mma_bf16(acc[0][1], ah0, bh01 + 2); mma_bf16(acc[0][1], ah0, bl01 + 2); mma_bf16(acc[0][1], al0, bh01 + 2);
            mma_bf16(acc[0][2], ah0, bh23 + 0); mma_bf16(acc[0][2], ah0, bl23 + 0); mma_bf16(acc[0][2], al0, bh23 + 0);
            mma_bf16(acc[0][3], ah0, bh23 + 2); mma_bf16(acc[0][3], ah0, bl23 + 2); mma_bf16(acc[0][3], al0, bh23 + 2);
            mma_bf16(acc[1][0], ah1, bh01 + 0); mma_bf16(acc[1][0], ah1, bl01 + 0); mma_bf16(acc[1][0], al1, bh01 + 0);
            mma_bf16(acc[1][1], ah1, bh01 + 2); mma_bf16(acc[1][1], ah1, bl01 + 2); mma_bf16(acc[1][1], al1, bh01 + 2);
            mma_bf16(acc[1][2], ah1, bh23 + 0); mma_bf16(acc[1][2], ah1, bl23 + 0); mma_bf16(acc[1][2], al1, bh23 + 0);
            mma_bf16(acc[1][3], ah1, bh23 + 2); mma_bf16(acc[1][3], ah1, bl23 + 2); mma_bf16(acc[1][3], al1, bh23 + 2);
        }
        __syncthreads();
    }
}

__device__ __forceinline__ void store_acc_mma(float* dst, int c0, float (&acc)[2][4][4])
{
    int lane = threadIdx.x & 31, wid = threadIdx.x >> 5;
    int wm = (wid & 1) * 32, wn = (wid >> 1) * 32;
    int r = lane >> 2, cc = (lane & 3) * 2;
    #pragma unroll
    for (int mt = 0; mt < 2; ++mt)
        #pragma unroll
        for (int ng = 0; ng < 4; ++ng) {
            int row = wm + mt * 16 + r;
            int col = c0 + wn + ng * 8 + cc;
            *(float2*)(dst + (size_t)row * HH + col)       = make_float2(acc[mt][ng][0], acc[mt][ng][1]);
            *(float2*)(dst + (size_t)(row + 8) * HH + col) = make_float2(acc[mt][ng][2], acc[mt][ng][3]);
        }
}

// ---------------- one-time: L0 input-half preactivations, all timesteps ----------------
// 41 KB smem, 124 regs -> 4 CTAs/SM fits; force it for latency overlap.
__global__ void __launch_bounds__(128, 4)
pre_kernel()
{
    __shared__ Stage st[2];
    int bid  = blockIdx.x;
    int job  = bid >> 11;            // 0..5
    int d    = job / 3;
    int gate = job % 3;
    int rem  = bid & 2047;
    int rowt = rem >> 3;             // 0..255
    int tile = rem & 7;              // 0..7

    const __nv_bfloat16* Ah = g_xh + (size_t)rowt * 64 * HH;
    const __nv_bfloat16* Al = g_xl + (size_t)rowt * 64 * HH;
    const __nv_bfloat16* Wh = g_Wh[gate] + (size_t)(d * 2 + 0) * HH * IND;
    const __nv_bfloat16* Wl = g_Wl[gate] + (size_t)(d * 2 + 0) * HH * IND;

    float acc[2][4][4] = {};
    gemm_mma(Ah, Al, Wh, Wl, 0, tile * 64, HH, acc, st);
    store_acc_mma(g_pin[d][gate] + (size_t)rowt * 64 * HH, tile * 64, acc);
}

// ---------------- the persistent recurrence kernel ----------------
// 448 blocks x 128 threads; 41 KB smem/CTA, regs capped 128 -> 4 CTAs/SM
// guaranteed residency (448 <= 592), ~3 CTAs/SM for latency overlap.
__global__ void __launch_bounds__(128, 4)
persist_kernel(const float* __restrict__ br, const float* __restrict__ bz,
               const float* __restrict__ bsv, float* __restrict__ dout)
{
    __shared__ Stage st[2];
    const int bid = blockIdx.x;
    const int tid = threadIdx.x;
    const int gtid = bid * 128 + tid;
    unsigned tgt = 0;

    for (int t = 0; t <= SQ; ++t) {
        // ============ P1: r/z GEMM slices + L1 s-input (all K=128, N=64 tiles) ============
        {
            const __nv_bfloat16 *Ah = 0, *Al = 0, *Wh = 0, *Wl = 0;
            float* dst = 0;
            int wk0 = 0, tile = 0, active = 0;
            if (bid < 128) {                        // L0 r/z: d,gate,slice(4),tile(8)
                if (t < SQ) {
                    int d     = (bid >> 6) & 1;
                    int gate  = (bid >> 5) & 1;
                    int slice = (bid >> 3) & 3;
                    tile      =  bid       & 7;
                    Ah = g_h0h[d][t & 1] + slice * 128;
                    Al = g_h0l[d][t & 1] + slice * 128;
                    Wh = g_Wh[gate] + (size_t)(d * 2 + 0) * HH * IND;
                    Wl = g_Wl[gate] + (size_t)(d * 2 + 0) * HH * IND;
                    wk0 = HH + slice * 128;
                    dst = g_paL0[d][gate][slice];
                    active = 1;
                }
            } else if (bid < 384) {                 // L1 r/z: d,gate,slice(8),tile(8)
                if (t >= 1) {
                    int q     = bid - 128;
                    int d     = (q >> 7) & 1;
                    int gate  = (q >> 6) & 1;
                    int slice = (q >> 3) & 7;
                    tile      =  q       & 7;
                    int u = t - 1;
                    if (slice < 4) {
                        Ah = g_y0h[d] + (size_t)u * BH + slice * 128;
                        Al = g_y0l[d] + (size_t)u * BH + slice * 128;
                    } else {
                        Ah = g_h1h[d][u & 1] + (slice - 4) * 128;
                        Al = g_h1l[d][u & 1] + (slice - 4) * 128;
                    }
                    Wh = g_Wh[gate] + (size_t)(d * 2 + 1) * HH * IND;
                    Wl = g_Wl[gate] + (size_t)(d * 2 + 1) * HH * IND;
                    wk0 = slice * 128;
                    dst = g_paL1[d][gate][slice];
                    active = 1;
                }
            } else {                                // L1 s-input: d,slice(4),tile(8)
                if (t >= 1) {
                    int q     = bid - 384;
                    int d     = (q >> 5) & 1;
                    int slice = (q >> 3) & 3;
                    tile      =  q       & 7;
                    int u = t - 1;
                    Ah = g_y0h[d] + (size_t)u * BH + slice * 128;
                    Al = g_y0l[d] + (size_t)u * BH + slice * 128;
                    Wh = g_Wh[2] + (size_t)(d * 2 + 1) * HH * IND;
                    Wl = g_Wl[2] + (size_t)(d * 2 + 1) * HH * IND;
                    wk0 = slice * 128;
                    dst = g_psp[d][slice];
                    active = 1;
                }
            }
            if (active) {
                float acc[2][4][4] = {};
                gemm_mma(Ah, Al, Wh, Wl, wk0, tile * 64, 128, acc, st);
                store_acc_mma(dst, tile * 64, acc);
            }
        }
        tgt += NBLK; grid_bar(tgt);

        // ============ P2: combA (r sigmoid + r*h split, z sigmoid) ============
        for (int e = gtid; e < 4 * BH; e += NBLK * 128) {
            int cell  = e >> 15;
            int layer = cell >> 1;
            int d     = cell & 1;
            if (layer == 0 && t >= SQ) continue;
            if (layer == 1 && t <  1 ) continue;
            int u   = (layer == 0) ? t : (t - 1);
            int idx = e & (BH - 1);
            int col = idx & 511;

            const float* h = (layer == 0) ? g_h0[d][u & 1] : g_h1[d][u & 1];
            float rpre, zpre;
            if (layer == 0) {
                int rt = d ? (SQ - 1 - t) : t;
                rpre = g_pin[d][0][(size_t)rt * BH + idx]
                     + g_paL0[d][0][0][idx] + g_paL0[d][0][1][idx]
                     + g_paL0[d][0][2][idx] + g_paL0[d][0][3][idx];
                zpre = g_pin[d][1][(size_t)rt * BH + idx]
                     + g_paL0[d][1][0][idx] + g_paL0[d][1][1][idx]
                     + g_paL0[d][1][2][idx] + g_paL0[d][1][3][idx];
            } else {
                rpre = zpre = 0.f;
                #pragma unroll
                for (int sl = 0; sl < 8; ++sl) {
                    rpre += g_paL1[d][0][sl][idx];
                    zpre += g_paL1[d][1][sl][idx];
                }
            }
            int boff = (d * 2 + layer) * HH + col;
            float rh = fsig(rpre + br[boff]) * h[idx];
            bfsplit(rh, g_rhh[layer][d][idx], g_rhl[layer][d][idx]);
            g_z[layer][d][idx] = fsig(zpre + bz[boff]);
        }
        tgt += NBLK; grid_bar(tgt);

        // ============ P3: s recurrent GEMM, K=512 in 8 slices of 64 ============
        if (bid < 256) {
            int layer = (bid >> 7) & 1;
            int d     = (bid >> 6) & 1;
            int slice = (bid >> 3) & 7;
            int tile  =  bid       & 7;
            int active = !((layer == 0 && t >= SQ) || (layer == 1 && t < 1));
            if (active) {
                const __nv_bfloat16* Ah = g_rhh[layer][d] + slice * 64;
                const __nv_bfloat16* Al = g_rhl[layer][d] + slice * 64;
                const __nv_bfloat16* Wh = g_Wh[2] + (size_t)(d * 2 + layer) * HH * IND;
                const __nv_bfloat16* Wl = g_Wl[2] + (size_t)(d * 2 + layer) * HH * IND;
                float acc[2][4][4] = {};
                gemm_mma(Ah, Al, Wh, Wl, HH + slice * 64, tile * 64, 64, acc, st);
                store_acc_mma(g_sp[layer][d][slice], tile * 64, acc);
            }
        }
        tgt += NBLK; grid_bar(tgt);

        // ============ P4: combS (tanh + mix + h update + splits + outputs) ============
        for (int e = gtid; e < 4 * BH; e += NBLK * 128) {
            int cell  = e >> 15;
            int layer = cell >> 1;
            int d     = cell & 1;
            if (layer == 0 && t >= SQ) continue;
            if (layer == 1 && t <  1 ) continue;
            int u   = (layer == 0) ? t : (t - 1);
            int idx = e & (BH - 1);
            int m   = idx >> 9;
            int col = idx & 511;

            float pre;
            if (layer == 0) {
                int rt = d ? (SQ - 1 - t) : t;
                pre = g_pin[d][2][(size_t)rt * BH + idx];
            } else {
                pre = g_psp[d][0][idx] + g_psp[d][1][idx]
                    + g_psp[d][2][idx] + g_psp[d][3][idx];
            }
            pre += bsv[(d * 2 + layer) * HH + col];
            #pragma unroll
            for (int sl = 0; sl < 8; ++sl)
                pre += g_sp[layer][d][sl][idx];

            float s = tanhf(pre);
            float z = g_z[layer][d][idx];

            const float* hp = (layer == 0) ? g_h0[d][u & 1]       : g_h1[d][u & 1];
            float*       hn = (layer == 0) ? g_h0[d][(u + 1) & 1] : g_h1[d][(u + 1) & 1];

            float h = z * hp[idx] + (1.f - z) * s;
            hn[idx] = h;
            if (layer == 0) {
                bfsplit(h, g_h0h[d][(u + 1) & 1][idx], g_h0l[d][(u + 1) & 1][idx]);
                bfsplit(h, g_y0h[d][(size_t)u * BH + idx], g_y0l[d][(size_t)u * BH + idx]);
                if (u == SQ - 1)
                    dout[OUT_SZ + (size_t)(d * 2 + 0) * BH + idx] = h;
            } else {
                bfsplit(h, g_h1h[d][(u + 1) & 1][idx], g_h1l[d][(u + 1) & 1][idx]);
                dout[(size_t)u * BB * (2 * HH) + (size_t)m * (2 * HH) + d * HH + col] = h;
                if (u == SQ - 1)
                    dout[OUT_SZ + (size_t)(d * 2 + 1) * BH + idx] = h;
            }
        }
        tgt += NBLK; grid_bar(tgt);
    }
}

// ---------------- launcher: 5 graph nodes ----------------
extern "C" void kernel_launch(void* const* d_in, const int* in_sizes, int n_in,
                              void* d_out, int out_size)
{
    const int*   tok = (const int*)  d_in[0];
    const float* emb = (const float*)d_in[1];
    const float* Wr  = (const float*)d_in[2];
    const float* Wz  = (const float*)d_in[3];
    const float* Wsv = (const float*)d_in[4];
    const float* br  = (const float*)d_in[5];
    const float* bz  = (const float*)d_in[6];
    const float* bsv = (const float*)d_in[7];
    float* outp = (float*)d_out;

    embed_kernel<<<SQ * BB, 128>>>(tok, emb);
    init_kernel<<<(BH + 255) / 256, 256>>>();
    {
        dim3 g((4 * HH * IND) / 256, 3);
        wsplit_kernel<<<g, 256>>>(Wr, Wz, Wsv);
    }
    pre_kernel<<<12288, 128>>>();
    persist_kernel<<<NBLK, 128>>>(br, bz, bsv, outp);
}